// round 15
// baseline (speedup 1.0000x reference)
#include <cuda_runtime.h>
#include <math.h>

#define T_STEPS 2048
#define BATCH   16
#define DDIM    1024
#define NPROJ   448           // 384 (kv) + 64 (q)
#define NOUT    (T_STEPS*BATCH*64)
#define MSIZE   (3*BATCH*64*64)
#define NSCAN   16
#define NCTA    148
#define NGEMM   (NCTA-NSCAN)
#define NRB     512           // row blocks of 64 proj rows (= 4 timesteps)
#define NTILES  (NRB*7)

__device__ float g_proj[(size_t)T_STEPS * BATCH * NPROJ];
__device__ float g_ssq[(size_t)T_STEPS * BATCH * 4];   // per-row k ssq (3 used)
__device__ int   g_cnt[NRB];

typedef unsigned long long ull;

__device__ __forceinline__ ull pk2(float lo, float hi) {
    ull r; asm("mov.b64 %0,{%1,%2};" : "=l"(r) : "f"(lo), "f"(hi)); return r;
}
__device__ __forceinline__ void upk2(ull v, float& a, float& b) {
    asm("mov.b64 {%0,%1},%2;" : "=f"(a), "=f"(b) : "l"(v));
}
__device__ __forceinline__ ull f2fma(ull a, ull b, ull c) {
    ull d; asm("fma.rn.f32x2 %0,%1,%2,%3;" : "=l"(d) : "l"(a), "l"(b), "l"(c)); return d;
}
__device__ __forceinline__ ull f2mul(ull a, ull b) {
    ull d; asm("mul.rn.f32x2 %0,%1,%2;" : "=l"(d) : "l"(a), "l"(b)); return d;
}
__device__ __forceinline__ int ldacq(const int* p) {
    int v; asm volatile("ld.acquire.gpu.global.b32 %0,[%1];" : "=r"(v) : "l"(p) : "memory"); return v;
}
__device__ __forceinline__ void redrel(int* p) {
    asm volatile("red.release.gpu.global.add.s32 [%0],1;" :: "l"(p) : "memory");
}
__device__ __forceinline__ unsigned smem_u32(const void* p) {
    unsigned a;
    asm("{.reg .u64 t; cvta.to.shared.u64 t,%1; cvt.u32.u64 %0,t;}" : "=r"(a) : "l"(p));
    return a;
}
__device__ __forceinline__ void cp16(unsigned dst, const void* src) {
    asm volatile("cp.async.cg.shared.global [%0],[%1],16;" :: "r"(dst), "l"(src) : "memory");
}
__device__ __forceinline__ void cp_commit() {
    asm volatile("cp.async.commit_group;" ::: "memory");
}
__device__ __forceinline__ void cp_wait1() {
    asm volatile("cp.async.wait_group 1;" ::: "memory");
}
__device__ __forceinline__ float sigm(float x) {
    return __fdividef(1.0f, 1.0f + __expf(-x));
}

__global__ void zero_cnt() { if (threadIdx.x < NRB) g_cnt[threadIdx.x] = 0; }

struct GemmS { float Xs[16][64]; float Ws[16][64]; };
struct ScanC {
    float raw[8][NPROJ];
    float kn[4][3][64];
    float cg[4][3][64];
    float rgdl[2][3][128];     // {rg[2p],rg[2p+1],dl[2p],dl[2p+1]}
    float ssq[8][4];
};

// ===========================================================================
// GEMM producer body; also emits per-row k-group sum-of-squares (cb 0/2/4).
// ===========================================================================
__device__ __forceinline__ void gemm_body(
    GemmS& G, int tid, int bx,
    const float* __restrict__ X, const float* __restrict__ Wkv,
    const float* __restrict__ Wq)
{
    const int tx = tid & 15;
    const int ty = tid >> 4;
    const int lr = tid >> 2;
    const int lc = (tid & 3) * 4;

    for (int tt = bx - NSCAN; tt < NTILES; tt += NGEMM) {
        const int rb = tt / 7, cb = tt % 7;
        const int bm = rb * 64, bn = cb * 64;

        float acc[4][4];
#pragma unroll
        for (int a = 0; a < 4; a++)
#pragma unroll
            for (int c = 0; c < 4; c++) acc[a][c] = 0.f;

        const float* xrow = X + (size_t)(bm + lr) * DDIM + lc;
        const int wr = bn + lr;
        const float* wrow = (wr < 384 ? Wkv + (size_t)wr * DDIM
                                      : Wq + (size_t)(wr - 384) * DDIM) + lc;

        for (int k0 = 0; k0 < DDIM; k0 += 16) {
            if (tid < 256) {
                float4 xv = *(const float4*)(xrow + k0);
                float4 wv = *(const float4*)(wrow + k0);
                G.Xs[lc + 0][lr] = xv.x; G.Xs[lc + 1][lr] = xv.y;
                G.Xs[lc + 2][lr] = xv.z; G.Xs[lc + 3][lr] = xv.w;
                G.Ws[lc + 0][lr] = wv.x; G.Ws[lc + 1][lr] = wv.y;
                G.Ws[lc + 2][lr] = wv.z; G.Ws[lc + 3][lr] = wv.w;
            }
            __syncthreads();
            if (tid < 256) {
#pragma unroll
                for (int kk = 0; kk < 16; kk++) {
                    float4 xr4 = *(const float4*)&G.Xs[kk][ty * 4];
                    float4 wr4 = *(const float4*)&G.Ws[kk][tx * 4];
                    float xa[4] = {xr4.x, xr4.y, xr4.z, xr4.w};
                    float wb[4] = {wr4.x, wr4.y, wr4.z, wr4.w};
#pragma unroll
                    for (int a = 0; a < 4; a++)
#pragma unroll
                        for (int c = 0; c < 4; c++)
                            acc[a][c] = fmaf(xa[a], wb[c], acc[a][c]);
                }
            }
            __syncthreads();
        }
        if (tid < 256) {
#pragma unroll
            for (int a = 0; a < 4; a++) {
                float4 o = {acc[a][0], acc[a][1], acc[a][2], acc[a][3]};
                *(float4*)&g_proj[(size_t)(bm + ty * 4 + a) * NPROJ + bn + tx * 4] = o;
            }
            if ((cb & 1) == 0 && cb < 6) {
                const int grp = cb >> 1;
                float p[4];
#pragma unroll
                for (int a = 0; a < 4; a++)
                    p[a] = acc[a][0]*acc[a][0] + acc[a][1]*acc[a][1]
                         + acc[a][2]*acc[a][2] + acc[a][3]*acc[a][3];
#pragma unroll
                for (int o = 1; o < 16; o <<= 1) {
#pragma unroll
                    for (int a = 0; a < 4; a++)
                        p[a] += __shfl_xor_sync(0xffffffffu, p[a], o);
                }
                if (tx == 0) {
#pragma unroll
                    for (int a = 0; a < 4; a++)
                        g_ssq[(size_t)(bm + ty * 4 + a) * 4 + grp] = p[a];
                }
            }
        }
        __syncthreads();
        if (tid == 0) redrel(&g_cnt[rb]);
    }
}

// ===========================================================================
// Variant F — no kgr retention (kn re-read in region B; ~120-reg demand),
// output deferred one step: the q-dot runs on PRE-update Mr2, interleaved
// with the gated update (operands shared), removing the serial q-dot tail
// from the critical warp. Epilogue emits the final step's output.
// ===========================================================================
__global__ __launch_bounds__(384, 1) void fusedF(
    const float* __restrict__ X, const float* __restrict__ Wkv,
    const float* __restrict__ Wq, const float* __restrict__ Mi,
    const float* __restrict__ Bg, float* __restrict__ out, int write_M)
{
    __shared__ __align__(16) union { GemmS g; ScanC s; } sm;
    const int tid = threadIdx.x;

    if (blockIdx.x >= NSCAN) { gemm_body(sm.g, tid, (int)blockIdx.x, X, Wkv, Wq); return; }

    const int b = blockIdx.x;
    const int g = tid >> 7, r = tid & 127, i = r >> 1, h = tid & 1;
    const int gm1 = (g + 2) % 3;
    const int wid = tid >> 5, lane = tid & 31;
    ScanC& S = sm.s;

    ull Mr2[16], MTr2[16];
    {
        const float* M0 = Mi + ((size_t)(g * BATCH + b)) * 4096;
#pragma unroll
        for (int j = 0; j < 16; j++) {
            float2 a = *(const float2*)&M0[i * 64 + 32 * h + 2 * j];
            Mr2[j]  = pk2(a.x, a.y);
            MTr2[j] = pk2(M0[(32 * h + 2 * j) * 64 + i],
                          M0[(32 * h + 2 * j + 1) * 64 + i]);
        }
    }
    const float bgm = Bg[gm1 * 64 + i];
    const bool pf = (tid >= 128 && tid < 240);
    const int  pidx = tid - 128;
    const bool knw = (wid >= 8 && wid < 11);
    const int  kw = wid - 8;
    int verified = 0;

    if (pf) {
        while (ldacq(&g_cnt[0]) < 7) __nanosleep(64);
#pragma unroll
        for (int rr = 0; rr < 3; rr++) {
            cp16(smem_u32(&S.raw[rr][pidx * 4]),
                 g_proj + (size_t)(rr * BATCH + b) * NPROJ + pidx * 4);
            if (pidx == 0)
                cp16(smem_u32(&S.ssq[rr][0]),
                     g_ssq + (size_t)(rr * BATCH + b) * 4);
            cp_commit();
        }
        cp16(smem_u32(&S.raw[3][pidx * 4]),
             g_proj + (size_t)(3 * BATCH + b) * NPROJ + pidx * 4);
        if (pidx == 0)
            cp16(smem_u32(&S.ssq[3][0]),
                 g_ssq + (size_t)(3 * BATCH + b) * 4);
        cp_commit();
        cp_wait1();
    }
    __syncthreads();
    if (knw) {
        float inv = __fdividef(1.0f, sqrtf(S.ssq[0][kw]) + 1e-6f);
        float a0 = S.raw[0][kw * 128 + lane];
        float a1 = S.raw[0][kw * 128 + 32 + lane];
        S.kn[0][kw][lane]      = a0 * inv;
        S.kn[0][kw][lane + 32] = a1 * inv;
    }
    __syncthreads();

    for (int t = 0; t < T_STEPS; t++) {
        const int cur = t & 7, b4 = t & 3, b2 = t & 1;
        const int nb4 = (t + 1) & 3;

        // ---- prefetch FIRST (LDG in flight during dots) ----
        if (pf) {
            const int t4 = t + 4;
            if (t4 < T_STEPS) {
                const int r4 = t4 * BATCH + b;
                const int rb4 = r4 >> 6;
                if (rb4 > verified) {
                    while (ldacq(&g_cnt[rb4]) < 7) __nanosleep(64);
                    verified = rb4;
                }
                cp16(smem_u32(&S.raw[t4 & 7][pidx * 4]),
                     g_proj + (size_t)r4 * NPROJ + pidx * 4);
                if (pidx == 0)
                    cp16(smem_u32(&S.ssq[t4 & 7][0]),
                         g_ssq + (size_t)r4 * 4);
            }
            cp_commit();
        }

        // preload v (broadcast LDS; hides under the dot chain)
        const float vval = S.raw[cur][g * 128 + 64 + i];

        // ---- dots (no kgr retention) ----
        ull rp = 0ull, ap = 0ull, cp = 0ull;
        {
            const ulonglong2* kg = (const ulonglong2*)(S.kn[b4][g]   + 32 * h);
            const ulonglong2* km = (const ulonglong2*)(S.kn[b4][gm1] + 32 * h);
#pragma unroll
            for (int j4 = 0; j4 < 8; j4++) {
                ulonglong2 kv  = kg[j4];
                ulonglong2 kmv = km[j4];
                rp = f2fma(Mr2[2 * j4],     kv.x,  rp);
                rp = f2fma(Mr2[2 * j4 + 1], kv.y,  rp);
                ap = f2fma(Mr2[2 * j4],     kmv.x, ap);
                ap = f2fma(Mr2[2 * j4 + 1], kmv.y, ap);
                cp = f2fma(MTr2[2 * j4],     kmv.x, cp);
                cp = f2fma(MTr2[2 * j4 + 1], kmv.y, cp);
            }
        }
        float rlo, rhi, alo, ahi, clo, chi;
        upk2(rp, rlo, rhi); upk2(ap, alo, ahi); upk2(cp, clo, chi);
        float rpart = rlo + rhi, apart = alo + ahi, cpart = clo + chi;
        rpart += __shfl_xor_sync(0xffffffffu, rpart, 1);
        apart += __shfl_xor_sync(0xffffffffu, apart, 1);
        cpart += __shfl_xor_sync(0xffffffffu, cpart, 1);
        const int pi = 4 * (i >> 1);
        if (!h) {
            S.rgdl[b2][gm1][pi + (i & 1)]     = sigm(apart + bgm);
            S.rgdl[b2][g]  [pi + 2 + (i & 1)] = vval - rpart;
        } else {
            S.cg[b4][gm1][i]                  = sigm(cpart + bgm);
        }

        // ---- kn for row t+1 (warps 8-10; ssq staged) ----
        if (knw && t + 1 < T_STEPS) {
            float inv = __fdividef(1.0f, sqrtf(S.ssq[(t + 1) & 7][kw]) + 1e-6f);
            float a0 = S.raw[(t + 1) & 7][kw * 128 + lane];
            float a1 = S.raw[(t + 1) & 7][kw * 128 + 32 + lane];
            S.kn[nb4][kw][lane]      = a0 * inv;
            S.kn[nb4][kw][lane + 32] = a1 * inv;
        }

        if (pf) cp_wait1();
        __syncthreads();

        // ---- region B: deferred output (t-1) interleaved with update ----
        const float cg_i = S.cg[b4][g][i];
        const float kn_i = S.kn[b4][g][i];
        const float rg_i = S.rgdl[b2][g][pi + (i & 1)];
        const float d_i  = S.rgdl[b2][g][pi + 2 + (i & 1)];
        const ull rgd = pk2(rg_i, rg_i), cgd = pk2(cg_i, cg_i);
        const ull dd  = pk2(d_i,  d_i),  knd = pk2(kn_i, kn_i);
        {
            const ulonglong2* cgp = (const ulonglong2*)(S.cg[b4][g] + 32 * h);
            const ulonglong2* knp = (const ulonglong2*)(S.kn[b4][g] + 32 * h);
            const ulonglong2* rd  = (const ulonglong2*)(S.rgdl[b2][g] + 64 * h);
            const ulonglong2* qp  =
                (const ulonglong2*)(S.raw[(t - 1) & 7] + 384 + 32 * h);
            const bool emit = (!g) && (t != 0);
            ull q0 = 0ull, q1 = 0ull;
#pragma unroll
            for (int j4 = 0; j4 < 8; j4++) {
                ulonglong2 cgv = cgp[j4];
                ulonglong2 knv = knp[j4];
                ulonglong2 bq0 = rd[2 * j4];
                ulonglong2 bq1 = rd[2 * j4 + 1];
                ull m0 = Mr2[2 * j4], m1 = Mr2[2 * j4 + 1];
                if (emit) {                       // q-dot on PRE-update M
                    ulonglong2 q = qp[j4];
                    q0 = f2fma(m0, q.x, q0);
                    q1 = f2fma(m1, q.y, q1);
                }
                Mr2[2*j4]   = f2fma(f2mul(m0, cgv.x), rgd,
                                    f2mul(knv.x, dd));
                Mr2[2*j4+1] = f2fma(f2mul(m1, cgv.y), rgd,
                                    f2mul(knv.y, dd));
                MTr2[2*j4]   = f2fma(f2mul(MTr2[2*j4],   bq0.x), cgd,
                                     f2mul(bq0.y, knd));
                MTr2[2*j4+1] = f2fma(f2mul(MTr2[2*j4+1], bq1.x), cgd,
                                     f2mul(bq1.y, knd));
            }
            if (emit) {
                float a0, a1, b0, b1;
                upk2(q0, a0, a1); upk2(q1, b0, b1);
                float s = (a0 + a1) + (b0 + b1);
                s += __shfl_xor_sync(0xffffffffu, s, 1);
                if (!h)
                    out[((size_t)(t - 1) * BATCH + b) * 64 + i] = s * sigm(s);
            }
        }
    }

    // epilogue: output for the final step (t = T_STEPS-1) on final M
    if (!g) {
        ull q0 = 0ull, q1 = 0ull;
        const ulonglong2* qp =
            (const ulonglong2*)(S.raw[(T_STEPS - 1) & 7] + 384 + 32 * h);
#pragma unroll
        for (int j4 = 0; j4 < 8; j4++) {
            ulonglong2 q = qp[j4];
            q0 = f2fma(Mr2[2 * j4],     q.x, q0);
            q1 = f2fma(Mr2[2 * j4 + 1], q.y, q1);
        }
        float a0, a1, b0, b1;
        upk2(q0, a0, a1); upk2(q1, b0, b1);
        float s = (a0 + a1) + (b0 + b1);
        s += __shfl_xor_sync(0xffffffffu, s, 1);
        if (!h)
            out[((size_t)(T_STEPS - 1) * BATCH + b) * 64 + i] = s * sigm(s);
    }

    if (write_M) {
        float* Mo = out + NOUT + ((size_t)(g * BATCH + b)) * 4096
                    + (size_t)i * 64 + 32 * h;
#pragma unroll
        for (int j = 0; j < 16; j++) {
            float a, c; upk2(Mr2[j], a, c);
            Mo[2 * j] = a; Mo[2 * j + 1] = c;
        }
    }
}

// ===========================================================================
// Variant C — EXACT R11 kernel (proven 2883us). Fallback only on true spill.
// ===========================================================================
__global__ __launch_bounds__(384, 1) void fusedC(
    const float* __restrict__ X, const float* __restrict__ Wkv,
    const float* __restrict__ Wq, const float* __restrict__ Mi,
    const float* __restrict__ Bg, float* __restrict__ out, int write_M)
{
    __shared__ __align__(16) union { GemmS g; ScanC s; } sm;
    const int tid = threadIdx.x;

    if (blockIdx.x >= NSCAN) { gemm_body(sm.g, tid, (int)blockIdx.x, X, Wkv, Wq); return; }

    const int b = blockIdx.x;
    const int g = tid >> 7, r = tid & 127, i = r >> 1, h = tid & 1;
    const int gm1 = (g + 2) % 3;
    const int wid = tid >> 5, lane = tid & 31;
    ScanC& S = sm.s;

    ull Mr2[16], MTr2[16];
    {
        const float* M0 = Mi + ((size_t)(g * BATCH + b)) * 4096;
#pragma unroll
        for (int j = 0; j < 16; j++) {
            float2 a = *(const float2*)&M0[i * 64 + 32 * h + 2 * j];
            Mr2[j]  = pk2(a.x, a.y);
            MTr2[j] = pk2(M0[(32 * h + 2 * j) * 64 + i],
                          M0[(32 * h + 2 * j + 1) * 64 + i]);
        }
    }
    const float bgm = Bg[gm1 * 64 + i];
    const bool pf = (tid >= 128 && tid < 240);
    const int  pidx = tid - 128;
    const bool knw = (wid >= 8 && wid < 11);
    const int  kw = wid - 8;
    int verified = 0;

    if (pf) {
        while (ldacq(&g_cnt[0]) < 7) __nanosleep(64);
#pragma unroll
        for (int rr = 0; rr < 3; rr++) {
            cp16(smem_u32(&S.raw[rr][pidx * 4]),
                 g_proj + (size_t)(rr * BATCH + b) * NPROJ + pidx * 4);
            if (pidx == 0)
                cp16(smem_u32(&S.ssq[rr][0]),
                     g_ssq + (size_t)(rr * BATCH + b) * 4);
            cp_commit();
        }
        cp16(smem_u32(&S.raw[3][pidx * 4]),
             g_proj + (size_t)(3 * BATCH + b) * NPROJ + pidx * 4);
        if (pidx == 0)
            cp16(smem_u32(&S.ssq[3][0]),
                 g_ssq + (size_t)(3 * BATCH + b) * 4);
        cp_commit();
        cp_wait1();
    }
    __syncthreads();
    if (knw) {
        float inv = __fdividef(1.0f, sqrtf(S.ssq[0][kw]) + 1e-6f);
        float a0 = S.raw[0][kw * 128 + lane];
        float a1 = S.raw[0][kw * 128 + 32 + lane];
        S.kn[0][kw][lane]      = a0 * inv;
        S.kn[0][kw][lane + 32] = a1 * inv;
    }
    __syncthreads();

    for (int t = 0; t < T_STEPS; t++) {
        const int cur = t & 7, b4 = t & 3, b2 = t & 1;
        const int nb4 = (t + 1) & 3;

        if (pf) {
            const int t4 = t + 4;
            if (t4 < T_STEPS) {
                const int r4 = t4 * BATCH + b;
                const int rb4 = r4 >> 6;
                if (rb4 > verified) {
                    while (ldacq(&g_cnt[rb4]) < 7) __nanosleep(64);
                    verified = rb4;
                }
                cp16(smem_u32(&S.raw[t4 & 7][pidx * 4]),
                     g_proj + (size_t)r4 * NPROJ + pidx * 4);
                if (pidx == 0)
                    cp16(smem_u32(&S.ssq[t4 & 7][0]),
                         g_ssq + (size_t)r4 * 4);
            }
            cp_commit();
        }

        ull kgr[16];
        ull rp = 0ull, ap = 0ull, cp = 0ull;
        {
            const ulonglong2* kg = (const ulonglong2*)(S.kn[b4][g]   + 32 * h);
            const ulonglong2* km = (const ulonglong2*)(S.kn[b4][gm1] + 32 * h);
#pragma unroll
            for (int j4 = 0; j4 < 8; j4++) {
                ulonglong2 kv  = kg[j4];
                ulonglong2 kmv = km[j4];
                kgr[2 * j4] = kv.x; kgr[2 * j4 + 1] = kv.y;
                rp = f2fma(Mr2[2 * j4],     kv.x,  rp);
                rp = f2fma(Mr2[2 * j4 + 1], kv.y,  rp);
                ap = f2fma(Mr2[2 * j4],     kmv.x, ap);
                ap = f2fma(Mr2[2 * j4 + 1], kmv.y, ap);
                cp = f2fma(MTr2[2 * j4],     kmv.x, cp);
                cp = f2fma(MTr2[2 * j4 + 1], kmv.y, cp);
            }
        }
        float rlo, rhi, alo, ahi, clo, chi;
        upk2(rp, rlo, rhi); upk2(ap, alo, ahi); upk2(cp, clo, chi);
        float rpart = rlo + rhi, apart = alo + ahi, cpart = clo + chi;
        rpart += __shfl_xor_sync(0xffffffffu, rpart, 1);
        apart += __shfl_xor_sync(0xffffffffu, apart, 1);
        cpart += __shfl_xor_sync(0xffffffffu, cpart, 1);
        const int pi = 4 * (i >> 1);
        if (!h) {
            S.rgdl[b2][gm1][pi + (i & 1)]     = sigm(apart + bgm);
            S.rgdl[b2][g]  [pi + 2 + (i & 1)] = S.raw[cur][g * 128 + 64 + i] - rpart;
        } else {
            S.cg[b4][gm1][i]                  = sigm(cpart + bgm);
        }

        if (knw && t + 1 < T_STEPS) {
            float inv = __fdividef(1.0f, sqrtf(S.ssq[(t + 1) & 7][kw]) + 1e-6f);
            float a0 = S.raw[(t + 1) & 7][kw * 128 + lane];
            float a1 = S.raw[(t + 1) & 7][kw * 128 + 32 + lane];
            S.kn[nb4][kw][lane]      = a0 * inv;
            S.kn[nb4][kw][lane + 32] = a1 * inv;
        }

        if (pf) cp_wait1();
        __syncthreads();

        const float cg_i = S.cg[b4][g][i];
        const float kn_i = S.kn[b4][g][i];
        const float rg_i = S.rgdl[b2][g][pi + (i & 1)];
        const float d_i  = S.rgdl[b2][g][pi + 2 + (i & 1)];
        const ull rgd = pk2(rg_i, rg_i), cgd = pk2(cg_i, cg_i);
        const ull dd  = pk2(d_i,  d_i),  knd = pk2(kn_i, kn_i);
        {
            const ulonglong2* cgp = (const ulonglong2*)(S.cg[b4][g] + 32 * h);
            const ulonglong2* rd  = (const ulonglong2*)(S.rgdl[b2][g] + 64 * h);
#pragma unroll
            for (int j4 = 0; j4 < 8; j4++) {
                ulonglong2 cgv = cgp[j4];
                ulonglong2 bq0 = rd[2 * j4];
                ulonglong2 bq1 = rd[2 * j4 + 1];
                Mr2[2*j4]   = f2fma(f2mul(Mr2[2*j4],   cgv.x), rgd,
                                    f2mul(kgr[2*j4],   dd));
                Mr2[2*j4+1] = f2fma(f2mul(Mr2[2*j4+1], cgv.y), rgd,
                                    f2mul(kgr[2*j4+1], dd));
                MTr2[2*j4]   = f2fma(f2mul(MTr2[2*j4],   bq0.x), cgd,
                                     f2mul(bq0.y, knd));
                MTr2[2*j4+1] = f2fma(f2mul(MTr2[2*j4+1], bq1.x), cgd,
                                     f2mul(bq1.y, knd));
            }
        }
        if (!g) {
            ull sq = 0ull;
            const ulonglong2* q2 = (const ulonglong2*)(S.raw[cur] + 384 + 32 * h);
#pragma unroll
            for (int j4 = 0; j4 < 8; j4++) {
                ulonglong2 q = q2[j4];
                sq = f2fma(Mr2[2 * j4],     q.x, sq);
                sq = f2fma(Mr2[2 * j4 + 1], q.y, sq);
            }
            float slo, shi; upk2(sq, slo, shi);
            float s = slo + shi;
            s += __shfl_xor_sync(0xffffffffu, s, 1);
            if (!h) out[((size_t)t * BATCH + b) * 64 + i] = s * sigm(s);
        }
    }

    if (write_M) {
        float* Mo = out + NOUT + ((size_t)(g * BATCH + b)) * 4096
                    + (size_t)i * 64 + 32 * h;
#pragma unroll
        for (int j = 0; j < 16; j++) {
            float a, c; upk2(Mr2[j], a, c);
            Mo[2 * j] = a; Mo[2 * j + 1] = c;
        }
    }
}

// ---------------------------------------------------------------------------
extern "C" void kernel_launch(void* const* d_in, const int* in_sizes, int n_in,
                              void* d_out, int out_size)
{
    const float *x = nullptr, *Mi = nullptr, *Wkv = nullptr,
                *Wq = nullptr, *Bg = nullptr;
    for (int idx = 0; idx < n_in; idx++) {
        switch (in_sizes[idx]) {
            case 33554432: x   = (const float*)d_in[idx]; break;
            case 196608:   Mi  = (const float*)d_in[idx]; break;
            case 393216:   Wkv = (const float*)d_in[idx]; break;
            case 65536:    Wq  = (const float*)d_in[idx]; break;
            case 192:      Bg  = (const float*)d_in[idx]; break;
        }
    }
    if (!x || !Mi || !Wkv || !Wq || !Bg) {
        x   = (const float*)d_in[0];
        Mi  = (const float*)d_in[1];
        Wkv = (const float*)d_in[2];
        Wq  = (const float*)d_in[3];
        Bg  = (const float*)d_in[4];
    }

    const int write_M = (out_size >= NOUT + MSIZE) ? 1 : 0;

    // Guard revised (R14 post-mortem): numRegs at the 168 cap is normal
    // budget-filling, NOT the cliff — demand here is ~120 (kgr removed).
    // Only a true spill (localSizeBytes > 0) falls back.
    cudaFuncAttributes attr;
    bool useF = true;
    if (cudaFuncGetAttributes(&attr, (const void*)fusedF) == cudaSuccess)
        useF = (attr.localSizeBytes == 0);

    zero_cnt<<<1, 512>>>();
    if (useF)
        fusedF<<<NCTA, 384>>>(x, Wkv, Wq, Mi, Bg, (float*)d_out, write_M);
    else
        fusedC<<<NCTA, 384>>>(x, Wkv, Wq, Mi, Bg, (float*)d_out, write_M);
}

// round 16
// speedup vs baseline: 1.1936x; 1.1936x over previous
#include <cuda_runtime.h>
#include <math.h>

#define T_STEPS 2048
#define BATCH   16
#define DDIM    1024
#define NPROJ   448           // 384 (kv) + 64 (q)
#define NOUT    (T_STEPS*BATCH*64)
#define MSIZE   (3*BATCH*64*64)
#define NSCAN   16
#define NCTA    148
#define NGEMM   (NCTA-NSCAN)
#define NRB     512           // row blocks of 64 proj rows (= 4 timesteps)
#define NTILES  (NRB*7)

__device__ float g_proj[(size_t)T_STEPS * BATCH * NPROJ];
__device__ float g_ssq[(size_t)T_STEPS * BATCH * 4];   // per-row k ssq (3 used)
__device__ int   g_cnt[NRB];

typedef unsigned long long ull;

__device__ __forceinline__ ull pk2(float lo, float hi) {
    ull r; asm("mov.b64 %0,{%1,%2};" : "=l"(r) : "f"(lo), "f"(hi)); return r;
}
__device__ __forceinline__ void upk2(ull v, float& a, float& b) {
    asm("mov.b64 {%0,%1},%2;" : "=f"(a), "=f"(b) : "l"(v));
}
__device__ __forceinline__ ull f2fma(ull a, ull b, ull c) {
    ull d; asm("fma.rn.f32x2 %0,%1,%2,%3;" : "=l"(d) : "l"(a), "l"(b), "l"(c)); return d;
}
__device__ __forceinline__ ull f2mul(ull a, ull b) {
    ull d; asm("mul.rn.f32x2 %0,%1,%2;" : "=l"(d) : "l"(a), "l"(b)); return d;
}
__device__ __forceinline__ int ldacq(const int* p) {
    int v; asm volatile("ld.acquire.gpu.global.b32 %0,[%1];" : "=r"(v) : "l"(p) : "memory"); return v;
}
__device__ __forceinline__ void redrel(int* p) {
    asm volatile("red.release.gpu.global.add.s32 [%0],1;" :: "l"(p) : "memory");
}
__device__ __forceinline__ unsigned smem_u32(const void* p) {
    unsigned a;
    asm("{.reg .u64 t; cvta.to.shared.u64 t,%1; cvt.u32.u64 %0,t;}" : "=r"(a) : "l"(p));
    return a;
}
__device__ __forceinline__ void cp16(unsigned dst, const void* src) {
    asm volatile("cp.async.cg.shared.global [%0],[%1],16;" :: "r"(dst), "l"(src) : "memory");
}
__device__ __forceinline__ void cp_commit() {
    asm volatile("cp.async.commit_group;" ::: "memory");
}
__device__ __forceinline__ void cp_wait1() {
    asm volatile("cp.async.wait_group 1;" ::: "memory");
}
__device__ __forceinline__ float sigm(float x) {
    return __fdividef(1.0f, 1.0f + __expf(-x));
}

__global__ void zero_cnt() { if (threadIdx.x < NRB) g_cnt[threadIdx.x] = 0; }

struct GemmS { float Xs[16][64]; float Ws[16][64]; };
struct ScanC {
    float raw[8][NPROJ];
    float kn[4][3][64];
    float cg[4][3][64];
    float rgdl[2][3][128];     // {rg[2p],rg[2p+1],dl[2p],dl[2p+1]}
    float ssq[8][4];
};

// ===========================================================================
// GEMM producer body; also emits per-row k-group sum-of-squares (cb 0/2/4).
// ===========================================================================
__device__ __forceinline__ void gemm_body(
    GemmS& G, int tid, int bx,
    const float* __restrict__ X, const float* __restrict__ Wkv,
    const float* __restrict__ Wq)
{
    const int tx = tid & 15;
    const int ty = tid >> 4;
    const int lr = tid >> 2;
    const int lc = (tid & 3) * 4;

    for (int tt = bx - NSCAN; tt < NTILES; tt += NGEMM) {
        const int rb = tt / 7, cb = tt % 7;
        const int bm = rb * 64, bn = cb * 64;

        float acc[4][4];
#pragma unroll
        for (int a = 0; a < 4; a++)
#pragma unroll
            for (int c = 0; c < 4; c++) acc[a][c] = 0.f;

        const float* xrow = X + (size_t)(bm + lr) * DDIM + lc;
        const int wr = bn + lr;
        const float* wrow = (wr < 384 ? Wkv + (size_t)wr * DDIM
                                      : Wq + (size_t)(wr - 384) * DDIM) + lc;

        for (int k0 = 0; k0 < DDIM; k0 += 16) {
            if (tid < 256) {
                float4 xv = *(const float4*)(xrow + k0);
                float4 wv = *(const float4*)(wrow + k0);
                G.Xs[lc + 0][lr] = xv.x; G.Xs[lc + 1][lr] = xv.y;
                G.Xs[lc + 2][lr] = xv.z; G.Xs[lc + 3][lr] = xv.w;
                G.Ws[lc + 0][lr] = wv.x; G.Ws[lc + 1][lr] = wv.y;
                G.Ws[lc + 2][lr] = wv.z; G.Ws[lc + 3][lr] = wv.w;
            }
            __syncthreads();
            if (tid < 256) {
#pragma unroll
                for (int kk = 0; kk < 16; kk++) {
                    float4 xr4 = *(const float4*)&G.Xs[kk][ty * 4];
                    float4 wr4 = *(const float4*)&G.Ws[kk][tx * 4];
                    float xa[4] = {xr4.x, xr4.y, xr4.z, xr4.w};
                    float wb[4] = {wr4.x, wr4.y, wr4.z, wr4.w};
#pragma unroll
                    for (int a = 0; a < 4; a++)
#pragma unroll
                        for (int c = 0; c < 4; c++)
                            acc[a][c] = fmaf(xa[a], wb[c], acc[a][c]);
                }
            }
            __syncthreads();
        }
        if (tid < 256) {
#pragma unroll
            for (int a = 0; a < 4; a++) {
                float4 o = {acc[a][0], acc[a][1], acc[a][2], acc[a][3]};
                *(float4*)&g_proj[(size_t)(bm + ty * 4 + a) * NPROJ + bn + tx * 4] = o;
            }
            if ((cb & 1) == 0 && cb < 6) {
                const int grp = cb >> 1;
                float p[4];
#pragma unroll
                for (int a = 0; a < 4; a++)
                    p[a] = acc[a][0]*acc[a][0] + acc[a][1]*acc[a][1]
                         + acc[a][2]*acc[a][2] + acc[a][3]*acc[a][3];
#pragma unroll
                for (int o = 1; o < 16; o <<= 1) {
#pragma unroll
                    for (int a = 0; a < 4; a++)
                        p[a] += __shfl_xor_sync(0xffffffffu, p[a], o);
                }
                if (tx == 0) {
#pragma unroll
                    for (int a = 0; a < 4; a++)
                        g_ssq[(size_t)(bm + ty * 4 + a) * 4 + grp] = p[a];
                }
            }
        }
        __syncthreads();
        if (tid == 0) redrel(&g_cnt[rb]);
    }
}

// ===========================================================================
// Variant G — fusedC (proven structure, kgr retained within-step) plus:
//   * convergent sigmoid (operand select before the call; no divergent
//     double-evaluation in the warp)
//   * vval preloaded before the dot chain
//   * q-dot split into 2 accumulators (registers reuse kgr's dead range)
// Arithmetic identical to fusedC.
// ===========================================================================
__global__ __launch_bounds__(384, 1) void fusedG(
    const float* __restrict__ X, const float* __restrict__ Wkv,
    const float* __restrict__ Wq, const float* __restrict__ Mi,
    const float* __restrict__ Bg, float* __restrict__ out, int write_M)
{
    __shared__ __align__(16) union { GemmS g; ScanC s; } sm;
    const int tid = threadIdx.x;

    if (blockIdx.x >= NSCAN) { gemm_body(sm.g, tid, (int)blockIdx.x, X, Wkv, Wq); return; }

    const int b = blockIdx.x;
    const int g = tid >> 7, r = tid & 127, i = r >> 1, h = tid & 1;
    const int gm1 = (g + 2) % 3;
    const int wid = tid >> 5, lane = tid & 31;
    ScanC& S = sm.s;

    ull Mr2[16], MTr2[16];
    {
        const float* M0 = Mi + ((size_t)(g * BATCH + b)) * 4096;
#pragma unroll
        for (int j = 0; j < 16; j++) {
            float2 a = *(const float2*)&M0[i * 64 + 32 * h + 2 * j];
            Mr2[j]  = pk2(a.x, a.y);
            MTr2[j] = pk2(M0[(32 * h + 2 * j) * 64 + i],
                          M0[(32 * h + 2 * j + 1) * 64 + i]);
        }
    }
    const float bgm = Bg[gm1 * 64 + i];
    const bool pf = (tid >= 128 && tid < 240);
    const int  pidx = tid - 128;
    const bool knw = (wid >= 8 && wid < 11);
    const int  kw = wid - 8;
    int verified = 0;

    if (pf) {
        while (ldacq(&g_cnt[0]) < 7) __nanosleep(64);
#pragma unroll
        for (int rr = 0; rr < 3; rr++) {
            cp16(smem_u32(&S.raw[rr][pidx * 4]),
                 g_proj + (size_t)(rr * BATCH + b) * NPROJ + pidx * 4);
            if (pidx == 0)
                cp16(smem_u32(&S.ssq[rr][0]),
                     g_ssq + (size_t)(rr * BATCH + b) * 4);
            cp_commit();
        }
        cp16(smem_u32(&S.raw[3][pidx * 4]),
             g_proj + (size_t)(3 * BATCH + b) * NPROJ + pidx * 4);
        if (pidx == 0)
            cp16(smem_u32(&S.ssq[3][0]),
                 g_ssq + (size_t)(3 * BATCH + b) * 4);
        cp_commit();
        cp_wait1();
    }
    __syncthreads();
    if (knw) {
        float inv = __fdividef(1.0f, sqrtf(S.ssq[0][kw]) + 1e-6f);
        float a0 = S.raw[0][kw * 128 + lane];
        float a1 = S.raw[0][kw * 128 + 32 + lane];
        S.kn[0][kw][lane]      = a0 * inv;
        S.kn[0][kw][lane + 32] = a1 * inv;
    }
    __syncthreads();

    for (int t = 0; t < T_STEPS; t++) {
        const int cur = t & 7, b4 = t & 3, b2 = t & 1;
        const int nb4 = (t + 1) & 3;

        // ---- prefetch FIRST (LDG in flight during dots) ----
        if (pf) {
            const int t4 = t + 4;
            if (t4 < T_STEPS) {
                const int r4 = t4 * BATCH + b;
                const int rb4 = r4 >> 6;
                if (rb4 > verified) {
                    while (ldacq(&g_cnt[rb4]) < 7) __nanosleep(64);
                    verified = rb4;
                }
                cp16(smem_u32(&S.raw[t4 & 7][pidx * 4]),
                     g_proj + (size_t)r4 * NPROJ + pidx * 4);
                if (pidx == 0)
                    cp16(smem_u32(&S.ssq[t4 & 7][0]),
                         g_ssq + (size_t)r4 * 4);
            }
            cp_commit();
        }

        // preload v (broadcast LDS; latency hides under the dot chain)
        const float vval = S.raw[cur][g * 128 + 64 + i];

        ull kgr[16];
        ull rp = 0ull, ap = 0ull, cp = 0ull;
        {
            const ulonglong2* kg = (const ulonglong2*)(S.kn[b4][g]   + 32 * h);
            const ulonglong2* km = (const ulonglong2*)(S.kn[b4][gm1] + 32 * h);
#pragma unroll
            for (int j4 = 0; j4 < 8; j4++) {
                ulonglong2 kv  = kg[j4];
                ulonglong2 kmv = km[j4];
                kgr[2 * j4] = kv.x; kgr[2 * j4 + 1] = kv.y;
                rp = f2fma(Mr2[2 * j4],     kv.x,  rp);
                rp = f2fma(Mr2[2 * j4 + 1], kv.y,  rp);
                ap = f2fma(Mr2[2 * j4],     kmv.x, ap);
                ap = f2fma(Mr2[2 * j4 + 1], kmv.y, ap);
                cp = f2fma(MTr2[2 * j4],     kmv.x, cp);
                cp = f2fma(MTr2[2 * j4 + 1], kmv.y, cp);
            }
        }
        float rlo, rhi, alo, ahi, clo, chi;
        upk2(rp, rlo, rhi); upk2(ap, alo, ahi); upk2(cp, clo, chi);
        float rpart = rlo + rhi, apart = alo + ahi, cpart = clo + chi;
        rpart += __shfl_xor_sync(0xffffffffu, rpart, 1);
        apart += __shfl_xor_sync(0xffffffffu, apart, 1);
        cpart += __shfl_xor_sync(0xffffffffu, cpart, 1);
        const int pi = 4 * (i >> 1);

        // ---- convergent sigmoid: one evaluation per lane, no divergent
        //      double-execution; only the cheap stores are predicated ----
        {
            const float pre  = (h ? cpart : apart) + bgm;
            const float gate = sigm(pre);
            if (!h) {
                S.rgdl[b2][gm1][pi + (i & 1)]     = gate;
                S.rgdl[b2][g]  [pi + 2 + (i & 1)] = vval - rpart;
            } else {
                S.cg[b4][gm1][i]                  = gate;
            }
        }

        // ---- kn for row t+1 (warps 8-10; ssq staged) ----
        if (knw && t + 1 < T_STEPS) {
            float inv = __fdividef(1.0f, sqrtf(S.ssq[(t + 1) & 7][kw]) + 1e-6f);
            float a0 = S.raw[(t + 1) & 7][kw * 128 + lane];
            float a1 = S.raw[(t + 1) & 7][kw * 128 + 32 + lane];
            S.kn[nb4][kw][lane]      = a0 * inv;
            S.kn[nb4][kw][lane + 32] = a1 * inv;
        }

        if (pf) cp_wait1();
        __syncthreads();

        // ---- region B: update (kgr, proven layout) + output ----
        const float cg_i = S.cg[b4][g][i];
        const float kn_i = S.kn[b4][g][i];
        const float rg_i = S.rgdl[b2][g][pi + (i & 1)];
        const float d_i  = S.rgdl[b2][g][pi + 2 + (i & 1)];
        const ull rgd = pk2(rg_i, rg_i), cgd = pk2(cg_i, cg_i);
        const ull dd  = pk2(d_i,  d_i),  knd = pk2(kn_i, kn_i);
        {
            const ulonglong2* cgp = (const ulonglong2*)(S.cg[b4][g] + 32 * h);
            const ulonglong2* rd  = (const ulonglong2*)(S.rgdl[b2][g] + 64 * h);
#pragma unroll
            for (int j4 = 0; j4 < 8; j4++) {
                ulonglong2 cgv = cgp[j4];
                ulonglong2 bq0 = rd[2 * j4];
                ulonglong2 bq1 = rd[2 * j4 + 1];
                Mr2[2*j4]   = f2fma(f2mul(Mr2[2*j4],   cgv.x), rgd,
                                    f2mul(kgr[2*j4],   dd));
                Mr2[2*j4+1] = f2fma(f2mul(Mr2[2*j4+1], cgv.y), rgd,
                                    f2mul(kgr[2*j4+1], dd));
                MTr2[2*j4]   = f2fma(f2mul(MTr2[2*j4],   bq0.x), cgd,
                                     f2mul(bq0.y, knd));
                MTr2[2*j4+1] = f2fma(f2mul(MTr2[2*j4+1], bq1.x), cgd,
                                     f2mul(bq1.y, knd));
            }
        }
        if (!g) {
            ull s0 = 0ull, s1 = 0ull;   // kgr dead here; registers reuse
            const ulonglong2* q2 = (const ulonglong2*)(S.raw[cur] + 384 + 32 * h);
#pragma unroll
            for (int j4 = 0; j4 < 8; j4++) {
                ulonglong2 q = q2[j4];
                s0 = f2fma(Mr2[2 * j4],     q.x, s0);
                s1 = f2fma(Mr2[2 * j4 + 1], q.y, s1);
            }
            float a0, a1, b0, b1;
            upk2(s0, a0, a1); upk2(s1, b0, b1);
            float s = (a0 + a1) + (b0 + b1);
            s += __shfl_xor_sync(0xffffffffu, s, 1);
            if (!h) out[((size_t)t * BATCH + b) * 64 + i] = s * sigm(s);
        }
    }

    if (write_M) {
        float* Mo = out + NOUT + ((size_t)(g * BATCH + b)) * 4096
                    + (size_t)i * 64 + 32 * h;
#pragma unroll
        for (int j = 0; j < 16; j++) {
            float a, c; upk2(Mr2[j], a, c);
            Mo[2 * j] = a; Mo[2 * j + 1] = c;
        }
    }
}

// ===========================================================================
// Variant C — EXACT R11 kernel (proven 2883us). Fallback only on true spill.
// ===========================================================================
__global__ __launch_bounds__(384, 1) void fusedC(
    const float* __restrict__ X, const float* __restrict__ Wkv,
    const float* __restrict__ Wq, const float* __restrict__ Mi,
    const float* __restrict__ Bg, float* __restrict__ out, int write_M)
{
    __shared__ __align__(16) union { GemmS g; ScanC s; } sm;
    const int tid = threadIdx.x;

    if (blockIdx.x >= NSCAN) { gemm_body(sm.g, tid, (int)blockIdx.x, X, Wkv, Wq); return; }

    const int b = blockIdx.x;
    const int g = tid >> 7, r = tid & 127, i = r >> 1, h = tid & 1;
    const int gm1 = (g + 2) % 3;
    const int wid = tid >> 5, lane = tid & 31;
    ScanC& S = sm.s;

    ull Mr2[16], MTr2[16];
    {
        const float* M0 = Mi + ((size_t)(g * BATCH + b)) * 4096;
#pragma unroll
        for (int j = 0; j < 16; j++) {
            float2 a = *(const float2*)&M0[i * 64 + 32 * h + 2 * j];
            Mr2[j]  = pk2(a.x, a.y);
            MTr2[j] = pk2(M0[(32 * h + 2 * j) * 64 + i],
                          M0[(32 * h + 2 * j + 1) * 64 + i]);
        }
    }
    const float bgm = Bg[gm1 * 64 + i];
    const bool pf = (tid >= 128 && tid < 240);
    const int  pidx = tid - 128;
    const bool knw = (wid >= 8 && wid < 11);
    const int  kw = wid - 8;
    int verified = 0;

    if (pf) {
        while (ldacq(&g_cnt[0]) < 7) __nanosleep(64);
#pragma unroll
        for (int rr = 0; rr < 3; rr++) {
            cp16(smem_u32(&S.raw[rr][pidx * 4]),
                 g_proj + (size_t)(rr * BATCH + b) * NPROJ + pidx * 4);
            if (pidx == 0)
                cp16(smem_u32(&S.ssq[rr][0]),
                     g_ssq + (size_t)(rr * BATCH + b) * 4);
            cp_commit();
        }
        cp16(smem_u32(&S.raw[3][pidx * 4]),
             g_proj + (size_t)(3 * BATCH + b) * NPROJ + pidx * 4);
        if (pidx == 0)
            cp16(smem_u32(&S.ssq[3][0]),
                 g_ssq + (size_t)(3 * BATCH + b) * 4);
        cp_commit();
        cp_wait1();
    }
    __syncthreads();
    if (knw) {
        float inv = __fdividef(1.0f, sqrtf(S.ssq[0][kw]) + 1e-6f);
        float a0 = S.raw[0][kw * 128 + lane];
        float a1 = S.raw[0][kw * 128 + 32 + lane];
        S.kn[0][kw][lane]      = a0 * inv;
        S.kn[0][kw][lane + 32] = a1 * inv;
    }
    __syncthreads();

    for (int t = 0; t < T_STEPS; t++) {
        const int cur = t & 7, b4 = t & 3, b2 = t & 1;
        const int nb4 = (t + 1) & 3;

        if (pf) {
            const int t4 = t + 4;
            if (t4 < T_STEPS) {
                const int r4 = t4 * BATCH + b;
                const int rb4 = r4 >> 6;
                if (rb4 > verified) {
                    while (ldacq(&g_cnt[rb4]) < 7) __nanosleep(64);
                    verified = rb4;
                }
                cp16(smem_u32(&S.raw[t4 & 7][pidx * 4]),
                     g_proj + (size_t)r4 * NPROJ + pidx * 4);
                if (pidx == 0)
                    cp16(smem_u32(&S.ssq[t4 & 7][0]),
                         g_ssq + (size_t)r4 * 4);
            }
            cp_commit();
        }

        ull kgr[16];
        ull rp = 0ull, ap = 0ull, cp = 0ull;
        {
            const ulonglong2* kg = (const ulonglong2*)(S.kn[b4][g]   + 32 * h);
            const ulonglong2* km = (const ulonglong2*)(S.kn[b4][gm1] + 32 * h);
#pragma unroll
            for (int j4 = 0; j4 < 8; j4++) {
                ulonglong2 kv  = kg[j4];
                ulonglong2 kmv = km[j4];
                kgr[2 * j4] = kv.x; kgr[2 * j4 + 1] = kv.y;
                rp = f2fma(Mr2[2 * j4],     kv.x,  rp);
                rp = f2fma(Mr2[2 * j4 + 1], kv.y,  rp);
                ap = f2fma(Mr2[2 * j4],     kmv.x, ap);
                ap = f2fma(Mr2[2 * j4 + 1], kmv.y, ap);
                cp = f2fma(MTr2[2 * j4],     kmv.x, cp);
                cp = f2fma(MTr2[2 * j4 + 1], kmv.y, cp);
            }
        }
        float rlo, rhi, alo, ahi, clo, chi;
        upk2(rp, rlo, rhi); upk2(ap, alo, ahi); upk2(cp, clo, chi);
        float rpart = rlo + rhi, apart = alo + ahi, cpart = clo + chi;
        rpart += __shfl_xor_sync(0xffffffffu, rpart, 1);
        apart += __shfl_xor_sync(0xffffffffu, apart, 1);
        cpart += __shfl_xor_sync(0xffffffffu, cpart, 1);
        const int pi = 4 * (i >> 1);
        if (!h) {
            S.rgdl[b2][gm1][pi + (i & 1)]     = sigm(apart + bgm);
            S.rgdl[b2][g]  [pi + 2 + (i & 1)] = S.raw[cur][g * 128 + 64 + i] - rpart;
        } else {
            S.cg[b4][gm1][i]                  = sigm(cpart + bgm);
        }

        if (knw && t + 1 < T_STEPS) {
            float inv = __fdividef(1.0f, sqrtf(S.ssq[(t + 1) & 7][kw]) + 1e-6f);
            float a0 = S.raw[(t + 1) & 7][kw * 128 + lane];
            float a1 = S.raw[(t + 1) & 7][kw * 128 + 32 + lane];
            S.kn[nb4][kw][lane]      = a0 * inv;
            S.kn[nb4][kw][lane + 32] = a1 * inv;
        }

        if (pf) cp_wait1();
        __syncthreads();

        const float cg_i = S.cg[b4][g][i];
        const float kn_i = S.kn[b4][g][i];
        const float rg_i = S.rgdl[b2][g][pi + (i & 1)];
        const float d_i  = S.rgdl[b2][g][pi + 2 + (i & 1)];
        const ull rgd = pk2(rg_i, rg_i), cgd = pk2(cg_i, cg_i);
        const ull dd  = pk2(d_i,  d_i),  knd = pk2(kn_i, kn_i);
        {
            const ulonglong2* cgp = (const ulonglong2*)(S.cg[b4][g] + 32 * h);
            const ulonglong2* rd  = (const ulonglong2*)(S.rgdl[b2][g] + 64 * h);
#pragma unroll
            for (int j4 = 0; j4 < 8; j4++) {
                ulonglong2 cgv = cgp[j4];
                ulonglong2 bq0 = rd[2 * j4];
                ulonglong2 bq1 = rd[2 * j4 + 1];
                Mr2[2*j4]   = f2fma(f2mul(Mr2[2*j4],   cgv.x), rgd,
                                    f2mul(kgr[2*j4],   dd));
                Mr2[2*j4+1] = f2fma(f2mul(Mr2[2*j4+1], cgv.y), rgd,
                                    f2mul(kgr[2*j4+1], dd));
                MTr2[2*j4]   = f2fma(f2mul(MTr2[2*j4],   bq0.x), cgd,
                                     f2mul(bq0.y, knd));
                MTr2[2*j4+1] = f2fma(f2mul(MTr2[2*j4+1], bq1.x), cgd,
                                     f2mul(bq1.y, knd));
            }
        }
        if (!g) {
            ull sq = 0ull;
            const ulonglong2* q2 = (const ulonglong2*)(S.raw[cur] + 384 + 32 * h);
#pragma unroll
            for (int j4 = 0; j4 < 8; j4++) {
                ulonglong2 q = q2[j4];
                sq = f2fma(Mr2[2 * j4],     q.x, sq);
                sq = f2fma(Mr2[2 * j4 + 1], q.y, sq);
            }
            float slo, shi; upk2(sq, slo, shi);
            float s = slo + shi;
            s += __shfl_xor_sync(0xffffffffu, s, 1);
            if (!h) out[((size_t)t * BATCH + b) * 64 + i] = s * sigm(s);
        }
    }

    if (write_M) {
        float* Mo = out + NOUT + ((size_t)(g * BATCH + b)) * 4096
                    + (size_t)i * 64 + 32 * h;
#pragma unroll
        for (int j = 0; j < 16; j++) {
            float a, c; upk2(Mr2[j], a, c);
            Mo[2 * j] = a; Mo[2 * j + 1] = c;
        }
    }
}

// ---------------------------------------------------------------------------
extern "C" void kernel_launch(void* const* d_in, const int* in_sizes, int n_in,
                              void* d_out, int out_size)
{
    const float *x = nullptr, *Mi = nullptr, *Wkv = nullptr,
                *Wq = nullptr, *Bg = nullptr;
    for (int idx = 0; idx < n_in; idx++) {
        switch (in_sizes[idx]) {
            case 33554432: x   = (const float*)d_in[idx]; break;
            case 196608:   Mi  = (const float*)d_in[idx]; break;
            case 393216:   Wkv = (const float*)d_in[idx]; break;
            case 65536:    Wq  = (const float*)d_in[idx]; break;
            case 192:      Bg  = (const float*)d_in[idx]; break;
        }
    }
    if (!x || !Mi || !Wkv || !Wq || !Bg) {
        x   = (const float*)d_in[0];
        Mi  = (const float*)d_in[1];
        Wkv = (const float*)d_in[2];
        Wq  = (const float*)d_in[3];
        Bg  = (const float*)d_in[4];
    }

    const int write_M = (out_size >= NOUT + MSIZE) ? 1 : 0;

    // Spill-only guard (R14/R15 lesson: regs at cap is benign budget-filling;
    // only localSizeBytes > 0 signals real trouble).
    cudaFuncAttributes attr;
    bool useG = true;
    if (cudaFuncGetAttributes(&attr, (const void*)fusedG) == cudaSuccess)
        useG = (attr.localSizeBytes == 0);

    zero_cnt<<<1, 512>>>();
    if (useG)
        fusedG<<<NCTA, 384>>>(x, Wkv, Wq, Mi, Bg, (float*)d_out, write_M);
    else
        fusedC<<<NCTA, 384>>>(x, Wkv, Wq, Mi, Bg, (float*)d_out, write_M);
}

// round 17
// speedup vs baseline: 1.2194x; 1.0216x over previous
#include <cuda_runtime.h>
#include <math.h>

#define T_STEPS 2048
#define BATCH   16
#define DDIM    1024
#define NPROJ   448           // 384 (kv) + 64 (q)
#define NOUT    (T_STEPS*BATCH*64)
#define MSIZE   (3*BATCH*64*64)
#define NSCAN   16
#define NCTA    148
#define NGEMM   (NCTA-NSCAN)
#define NRB     512           // row blocks of 64 proj rows (= 4 timesteps)
#define NTILES  (NRB*7)

__device__ float g_proj[(size_t)T_STEPS * BATCH * NPROJ];
__device__ float g_ssq[(size_t)T_STEPS * BATCH * 4];   // used by fallback G only
__device__ int   g_cnt[NRB];

typedef unsigned long long ull;

__device__ __forceinline__ ull pk2(float lo, float hi) {
    ull r; asm("mov.b64 %0,{%1,%2};" : "=l"(r) : "f"(lo), "f"(hi)); return r;
}
__device__ __forceinline__ void upk2(ull v, float& a, float& b) {
    asm("mov.b64 {%0,%1},%2;" : "=f"(a), "=f"(b) : "l"(v));
}
__device__ __forceinline__ ull f2fma(ull a, ull b, ull c) {
    ull d; asm("fma.rn.f32x2 %0,%1,%2,%3;" : "=l"(d) : "l"(a), "l"(b), "l"(c)); return d;
}
__device__ __forceinline__ ull f2mul(ull a, ull b) {
    ull d; asm("mul.rn.f32x2 %0,%1,%2;" : "=l"(d) : "l"(a), "l"(b)); return d;
}
__device__ __forceinline__ int ldacq(const int* p) {
    int v; asm volatile("ld.acquire.gpu.global.b32 %0,[%1];" : "=r"(v) : "l"(p) : "memory"); return v;
}
__device__ __forceinline__ void redrel(int* p) {
    asm volatile("red.release.gpu.global.add.s32 [%0],1;" :: "l"(p) : "memory");
}
__device__ __forceinline__ unsigned smem_u32(const void* p) {
    unsigned a;
    asm("{.reg .u64 t; cvta.to.shared.u64 t,%1; cvt.u32.u64 %0,t;}" : "=r"(a) : "l"(p));
    return a;
}
__device__ __forceinline__ void cp16(unsigned dst, const void* src) {
    asm volatile("cp.async.cg.shared.global [%0],[%1],16;" :: "r"(dst), "l"(src) : "memory");
}
__device__ __forceinline__ void cp_commit() {
    asm volatile("cp.async.commit_group;" ::: "memory");
}
__device__ __forceinline__ void cp_wait1() {
    asm volatile("cp.async.wait_group 1;" ::: "memory");
}
__device__ __forceinline__ float sigm(float x) {
    return __fdividef(1.0f, 1.0f + __expf(-x));
}

__global__ void zero_cnt() { if (threadIdx.x < NRB) g_cnt[threadIdx.x] = 0; }

struct GemmS { float Xs[16][64]; float Ws[16][64]; };
struct ScanH {                 // kn pre-normalized in g_proj: no kn/ssq smem
    float raw[8][NPROJ];
    float cg[4][3][64];
    float rgdl[2][3][128];     // {rg[2p],rg[2p+1],dl[2p],dl[2p+1]}
};
struct ScanC {                 // fallback layout (fusedG)
    float raw[8][NPROJ];
    float kn[4][3][64];
    float cg[4][3][64];
    float rgdl[2][3][128];
    float ssq[8][4];
};

// ===========================================================================
// GEMM producer body. For k tiles (cb 0/2/4): computes row sum-of-squares,
// NORMALIZES the tile in-register (kn = k/(||k||+eps)), stores kn directly.
// Also stores ssq to g_ssq (fallback kernel needs it). v/q tiles unchanged.
// ===========================================================================
__device__ __forceinline__ void gemm_body(
    GemmS& G, int tid, int bx,
    const float* __restrict__ X, const float* __restrict__ Wkv,
    const float* __restrict__ Wq, int normalize_k)
{
    const int tx = tid & 15;
    const int ty = tid >> 4;
    const int lr = tid >> 2;
    const int lc = (tid & 3) * 4;

    for (int tt = bx - NSCAN; tt < NTILES; tt += NGEMM) {
        const int rb = tt / 7, cb = tt % 7;
        const int bm = rb * 64, bn = cb * 64;

        float acc[4][4];
#pragma unroll
        for (int a = 0; a < 4; a++)
#pragma unroll
            for (int c = 0; c < 4; c++) acc[a][c] = 0.f;

        const float* xrow = X + (size_t)(bm + lr) * DDIM + lc;
        const int wr = bn + lr;
        const float* wrow = (wr < 384 ? Wkv + (size_t)wr * DDIM
                                      : Wq + (size_t)(wr - 384) * DDIM) + lc;

        for (int k0 = 0; k0 < DDIM; k0 += 16) {
            if (tid < 256) {
                float4 xv = *(const float4*)(xrow + k0);
                float4 wv = *(const float4*)(wrow + k0);
                G.Xs[lc + 0][lr] = xv.x; G.Xs[lc + 1][lr] = xv.y;
                G.Xs[lc + 2][lr] = xv.z; G.Xs[lc + 3][lr] = xv.w;
                G.Ws[lc + 0][lr] = wv.x; G.Ws[lc + 1][lr] = wv.y;
                G.Ws[lc + 2][lr] = wv.z; G.Ws[lc + 3][lr] = wv.w;
            }
            __syncthreads();
            if (tid < 256) {
#pragma unroll
                for (int kk = 0; kk < 16; kk++) {
                    float4 xr4 = *(const float4*)&G.Xs[kk][ty * 4];
                    float4 wr4 = *(const float4*)&G.Ws[kk][tx * 4];
                    float xa[4] = {xr4.x, xr4.y, xr4.z, xr4.w};
                    float wb[4] = {wr4.x, wr4.y, wr4.z, wr4.w};
#pragma unroll
                    for (int a = 0; a < 4; a++)
#pragma unroll
                        for (int c = 0; c < 4; c++)
                            acc[a][c] = fmaf(xa[a], wb[c], acc[a][c]);
                }
            }
            __syncthreads();
        }
        if (tid < 256) {
            if ((cb & 1) == 0 && cb < 6) {
                const int grp = cb >> 1;
                float p[4];
#pragma unroll
                for (int a = 0; a < 4; a++)
                    p[a] = acc[a][0]*acc[a][0] + acc[a][1]*acc[a][1]
                         + acc[a][2]*acc[a][2] + acc[a][3]*acc[a][3];
#pragma unroll
                for (int o = 1; o < 16; o <<= 1) {
#pragma unroll
                    for (int a = 0; a < 4; a++)
                        p[a] += __shfl_xor_sync(0xffffffffu, p[a], o);
                }
                if (tx == 0) {
#pragma unroll
                    for (int a = 0; a < 4; a++)
                        g_ssq[(size_t)(bm + ty * 4 + a) * 4 + grp] = p[a];
                }
                if (normalize_k) {      // store kn = k * 1/(sqrt(ssq)+eps)
#pragma unroll
                    for (int a = 0; a < 4; a++) {
                        float inv = __fdividef(1.0f, sqrtf(p[a]) + 1e-6f);
#pragma unroll
                        for (int c = 0; c < 4; c++) acc[a][c] *= inv;
                    }
                }
            }
#pragma unroll
            for (int a = 0; a < 4; a++) {
                float4 o = {acc[a][0], acc[a][1], acc[a][2], acc[a][3]};
                *(float4*)&g_proj[(size_t)(bm + ty * 4 + a) * NPROJ + bn + tx * 4] = o;
            }
        }
        __syncthreads();
        if (tid == 0) redrel(&g_cnt[rb]);
    }
}

// ===========================================================================
// Variant H — producer-normalized kn: raw[cur] IS the kn buffer. No kn-next
// duty, no kn/ssq smem, uniform A-legs. Otherwise identical to fusedG
// (kgr retention, convergent sigmoid, vval preload, split q-dot).
// ===========================================================================
__global__ __launch_bounds__(384, 1) void fusedH(
    const float* __restrict__ X, const float* __restrict__ Wkv,
    const float* __restrict__ Wq, const float* __restrict__ Mi,
    const float* __restrict__ Bg, float* __restrict__ out, int write_M)
{
    __shared__ __align__(16) union { GemmS g; ScanH s; } sm;
    const int tid = threadIdx.x;

    if (blockIdx.x >= NSCAN) {
        gemm_body(sm.g, tid, (int)blockIdx.x, X, Wkv, Wq, 1);
        return;
    }

    const int b = blockIdx.x;
    const int g = tid >> 7, r = tid & 127, i = r >> 1, h = tid & 1;
    const int gm1 = (g + 2) % 3;
    ScanH& S = sm.s;

    ull Mr2[16], MTr2[16];
    {
        const float* M0 = Mi + ((size_t)(g * BATCH + b)) * 4096;
#pragma unroll
        for (int j = 0; j < 16; j++) {
            float2 a = *(const float2*)&M0[i * 64 + 32 * h + 2 * j];
            Mr2[j]  = pk2(a.x, a.y);
            MTr2[j] = pk2(M0[(32 * h + 2 * j) * 64 + i],
                          M0[(32 * h + 2 * j + 1) * 64 + i]);
        }
    }
    const float bgm = Bg[gm1 * 64 + i];
    const bool pf = (tid >= 128 && tid < 240);
    const int  pidx = tid - 128;
    int verified = 0;

    // prologue: stage rows 0..2, issue row 3
    if (pf) {
        while (ldacq(&g_cnt[0]) < 7) __nanosleep(64);
#pragma unroll
        for (int rr = 0; rr < 3; rr++) {
            cp16(smem_u32(&S.raw[rr][pidx * 4]),
                 g_proj + (size_t)(rr * BATCH + b) * NPROJ + pidx * 4);
            cp_commit();
        }
        cp16(smem_u32(&S.raw[3][pidx * 4]),
             g_proj + (size_t)(3 * BATCH + b) * NPROJ + pidx * 4);
        cp_commit();
        cp_wait1();
    }
    __syncthreads();

    for (int t = 0; t < T_STEPS; t++) {
        const int cur = t & 7, b4 = t & 3, b2 = t & 1;

        // ---- prefetch FIRST (LDG in flight during dots) ----
        if (pf) {
            const int t4 = t + 4;
            if (t4 < T_STEPS) {
                const int r4 = t4 * BATCH + b;
                const int rb4 = r4 >> 6;
                if (rb4 > verified) {
                    while (ldacq(&g_cnt[rb4]) < 7) __nanosleep(64);
                    verified = rb4;
                }
                cp16(smem_u32(&S.raw[t4 & 7][pidx * 4]),
                     g_proj + (size_t)r4 * NPROJ + pidx * 4);
            }
            cp_commit();
        }

        // preload v (broadcast LDS; latency hides under the dot chain)
        const float vval = S.raw[cur][g * 128 + 64 + i];

        ull kgr[16];
        ull rp = 0ull, ap = 0ull, cp = 0ull;
        {
            const ulonglong2* kg = (const ulonglong2*)(S.raw[cur] + g   * 128 + 32 * h);
            const ulonglong2* km = (const ulonglong2*)(S.raw[cur] + gm1 * 128 + 32 * h);
#pragma unroll
            for (int j4 = 0; j4 < 8; j4++) {
                ulonglong2 kv  = kg[j4];
                ulonglong2 kmv = km[j4];
                kgr[2 * j4] = kv.x; kgr[2 * j4 + 1] = kv.y;
                rp = f2fma(Mr2[2 * j4],     kv.x,  rp);
                rp = f2fma(Mr2[2 * j4 + 1], kv.y,  rp);
                ap = f2fma(Mr2[2 * j4],     kmv.x, ap);
                ap = f2fma(Mr2[2 * j4 + 1], kmv.y, ap);
                cp = f2fma(MTr2[2 * j4],     kmv.x, cp);
                cp = f2fma(MTr2[2 * j4 + 1], kmv.y, cp);
            }
        }
        float rlo, rhi, alo, ahi, clo, chi;
        upk2(rp, rlo, rhi); upk2(ap, alo, ahi); upk2(cp, clo, chi);
        float rpart = rlo + rhi, apart = alo + ahi, cpart = clo + chi;
        rpart += __shfl_xor_sync(0xffffffffu, rpart, 1);
        apart += __shfl_xor_sync(0xffffffffu, apart, 1);
        cpart += __shfl_xor_sync(0xffffffffu, cpart, 1);
        const int pi = 4 * (i >> 1);

        // convergent sigmoid (one evaluation per lane)
        {
            const float pre  = (h ? cpart : apart) + bgm;
            const float gate = sigm(pre);
            if (!h) {
                S.rgdl[b2][gm1][pi + (i & 1)]     = gate;
                S.rgdl[b2][g]  [pi + 2 + (i & 1)] = vval - rpart;
            } else {
                S.cg[b4][gm1][i]                  = gate;
            }
        }

        if (pf) cp_wait1();
        __syncthreads();

        // ---- region B: update (kgr from regs) + output ----
        const float cg_i = S.cg[b4][g][i];
        const float kn_i = S.raw[cur][g * 128 + i];
        const float rg_i = S.rgdl[b2][g][pi + (i & 1)];
        const float d_i  = S.rgdl[b2][g][pi + 2 + (i & 1)];
        const ull rgd = pk2(rg_i, rg_i), cgd = pk2(cg_i, cg_i);
        const ull dd  = pk2(d_i,  d_i),  knd = pk2(kn_i, kn_i);
        {
            const ulonglong2* cgp = (const ulonglong2*)(S.cg[b4][g] + 32 * h);
            const ulonglong2* rd  = (const ulonglong2*)(S.rgdl[b2][g] + 64 * h);
#pragma unroll
            for (int j4 = 0; j4 < 8; j4++) {
                ulonglong2 cgv = cgp[j4];
                ulonglong2 bq0 = rd[2 * j4];
                ulonglong2 bq1 = rd[2 * j4 + 1];
                Mr2[2*j4]   = f2fma(f2mul(Mr2[2*j4],   cgv.x), rgd,
                                    f2mul(kgr[2*j4],   dd));
                Mr2[2*j4+1] = f2fma(f2mul(Mr2[2*j4+1], cgv.y), rgd,
                                    f2mul(kgr[2*j4+1], dd));
                MTr2[2*j4]   = f2fma(f2mul(MTr2[2*j4],   bq0.x), cgd,
                                     f2mul(bq0.y, knd));
                MTr2[2*j4+1] = f2fma(f2mul(MTr2[2*j4+1], bq1.x), cgd,
                                     f2mul(bq1.y, knd));
            }
        }
        if (!g) {
            ull s0 = 0ull, s1 = 0ull;   // kgr dead; registers reuse
            const ulonglong2* q2 = (const ulonglong2*)(S.raw[cur] + 384 + 32 * h);
#pragma unroll
            for (int j4 = 0; j4 < 8; j4++) {
                ulonglong2 q = q2[j4];
                s0 = f2fma(Mr2[2 * j4],     q.x, s0);
                s1 = f2fma(Mr2[2 * j4 + 1], q.y, s1);
            }
            float a0, a1, b0, b1;
            upk2(s0, a0, a1); upk2(s1, b0, b1);
            float s = (a0 + a1) + (b0 + b1);
            s += __shfl_xor_sync(0xffffffffu, s, 1);
            if (!h) out[((size_t)t * BATCH + b) * 64 + i] = s * sigm(s);
        }
    }

    if (write_M) {
        float* Mo = out + NOUT + ((size_t)(g * BATCH + b)) * 4096
                    + (size_t)i * 64 + 32 * h;
#pragma unroll
        for (int j = 0; j < 16; j++) {
            float a, c; upk2(Mr2[j], a, c);
            Mo[2 * j] = a; Mo[2 * j + 1] = c;
        }
    }
}

// ===========================================================================
// Variant G — EXACT R16 kernel (proven 2819us). Fallback only on true spill.
// Uses un-normalized k + staged ssq (gemm normalize_k=0).
// ===========================================================================
__global__ __launch_bounds__(384, 1) void fusedG(
    const float* __restrict__ X, const float* __restrict__ Wkv,
    const float* __restrict__ Wq, const float* __restrict__ Mi,
    const float* __restrict__ Bg, float* __restrict__ out, int write_M)
{
    __shared__ __align__(16) union { GemmS g; ScanC s; } sm;
    const int tid = threadIdx.x;

    if (blockIdx.x >= NSCAN) {
        gemm_body(sm.g, tid, (int)blockIdx.x, X, Wkv, Wq, 0);
        return;
    }

    const int b = blockIdx.x;
    const int g = tid >> 7, r = tid & 127, i = r >> 1, h = tid & 1;
    const int gm1 = (g + 2) % 3;
    const int wid = tid >> 5, lane = tid & 31;
    ScanC& S = sm.s;

    ull Mr2[16], MTr2[16];
    {
        const float* M0 = Mi + ((size_t)(g * BATCH + b)) * 4096;
#pragma unroll
        for (int j = 0; j < 16; j++) {
            float2 a = *(const float2*)&M0[i * 64 + 32 * h + 2 * j];
            Mr2[j]  = pk2(a.x, a.y);
            MTr2[j] = pk2(M0[(32 * h + 2 * j) * 64 + i],
                          M0[(32 * h + 2 * j + 1) * 64 + i]);
        }
    }
    const float bgm = Bg[gm1 * 64 + i];
    const bool pf = (tid >= 128 && tid < 240);
    const int  pidx = tid - 128;
    const bool knw = (wid >= 8 && wid < 11);
    const int  kw = wid - 8;
    int verified = 0;

    if (pf) {
        while (ldacq(&g_cnt[0]) < 7) __nanosleep(64);
#pragma unroll
        for (int rr = 0; rr < 3; rr++) {
            cp16(smem_u32(&S.raw[rr][pidx * 4]),
                 g_proj + (size_t)(rr * BATCH + b) * NPROJ + pidx * 4);
            if (pidx == 0)
                cp16(smem_u32(&S.ssq[rr][0]),
                     g_ssq + (size_t)(rr * BATCH + b) * 4);
            cp_commit();
        }
        cp16(smem_u32(&S.raw[3][pidx * 4]),
             g_proj + (size_t)(3 * BATCH + b) * NPROJ + pidx * 4);
        if (pidx == 0)
            cp16(smem_u32(&S.ssq[3][0]),
                 g_ssq + (size_t)(3 * BATCH + b) * 4);
        cp_commit();
        cp_wait1();
    }
    __syncthreads();
    if (knw) {
        float inv = __fdividef(1.0f, sqrtf(S.ssq[0][kw]) + 1e-6f);
        float a0 = S.raw[0][kw * 128 + lane];
        float a1 = S.raw[0][kw * 128 + 32 + lane];
        S.kn[0][kw][lane]      = a0 * inv;
        S.kn[0][kw][lane + 32] = a1 * inv;
    }
    __syncthreads();

    for (int t = 0; t < T_STEPS; t++) {
        const int cur = t & 7, b4 = t & 3, b2 = t & 1;
        const int nb4 = (t + 1) & 3;

        if (pf) {
            const int t4 = t + 4;
            if (t4 < T_STEPS) {
                const int r4 = t4 * BATCH + b;
                const int rb4 = r4 >> 6;
                if (rb4 > verified) {
                    while (ldacq(&g_cnt[rb4]) < 7) __nanosleep(64);
                    verified = rb4;
                }
                cp16(smem_u32(&S.raw[t4 & 7][pidx * 4]),
                     g_proj + (size_t)r4 * NPROJ + pidx * 4);
                if (pidx == 0)
                    cp16(smem_u32(&S.ssq[t4 & 7][0]),
                         g_ssq + (size_t)r4 * 4);
            }
            cp_commit();
        }

        const float vval = S.raw[cur][g * 128 + 64 + i];

        ull kgr[16];
        ull rp = 0ull, ap = 0ull, cp = 0ull;
        {
            const ulonglong2* kg = (const ulonglong2*)(S.kn[b4][g]   + 32 * h);
            const ulonglong2* km = (const ulonglong2*)(S.kn[b4][gm1] + 32 * h);
#pragma unroll
            for (int j4 = 0; j4 < 8; j4++) {
                ulonglong2 kv  = kg[j4];
                ulonglong2 kmv = km[j4];
                kgr[2 * j4] = kv.x; kgr[2 * j4 + 1] = kv.y;
                rp = f2fma(Mr2[2 * j4],     kv.x,  rp);
                rp = f2fma(Mr2[2 * j4 + 1], kv.y,  rp);
                ap = f2fma(Mr2[2 * j4],     kmv.x, ap);
                ap = f2fma(Mr2[2 * j4 + 1], kmv.y, ap);
                cp = f2fma(MTr2[2 * j4],     kmv.x, cp);
                cp = f2fma(MTr2[2 * j4 + 1], kmv.y, cp);
            }
        }
        float rlo, rhi, alo, ahi, clo, chi;
        upk2(rp, rlo, rhi); upk2(ap, alo, ahi); upk2(cp, clo, chi);
        float rpart = rlo + rhi, apart = alo + ahi, cpart = clo + chi;
        rpart += __shfl_xor_sync(0xffffffffu, rpart, 1);
        apart += __shfl_xor_sync(0xffffffffu, apart, 1);
        cpart += __shfl_xor_sync(0xffffffffu, cpart, 1);
        const int pi = 4 * (i >> 1);
        {
            const float pre  = (h ? cpart : apart) + bgm;
            const float gate = sigm(pre);
            if (!h) {
                S.rgdl[b2][gm1][pi + (i & 1)]     = gate;
                S.rgdl[b2][g]  [pi + 2 + (i & 1)] = vval - rpart;
            } else {
                S.cg[b4][gm1][i]                  = gate;
            }
        }

        if (knw && t + 1 < T_STEPS) {
            float inv = __fdividef(1.0f, sqrtf(S.ssq[(t + 1) & 7][kw]) + 1e-6f);
            float a0 = S.raw[(t + 1) & 7][kw * 128 + lane];
            float a1 = S.raw[(t + 1) & 7][kw * 128 + 32 + lane];
            S.kn[nb4][kw][lane]      = a0 * inv;
            S.kn[nb4][kw][lane + 32] = a1 * inv;
        }

        if (pf) cp_wait1();
        __syncthreads();

        const float cg_i = S.cg[b4][g][i];
        const float kn_i = S.kn[b4][g][i];
        const float rg_i = S.rgdl[b2][g][pi + (i & 1)];
        const float d_i  = S.rgdl[b2][g][pi + 2 + (i & 1)];
        const ull rgd = pk2(rg_i, rg_i), cgd = pk2(cg_i, cg_i);
        const ull dd  = pk2(d_i,  d_i),  knd = pk2(kn_i, kn_i);
        {
            const ulonglong2* cgp = (const ulonglong2*)(S.cg[b4][g] + 32 * h);
            const ulonglong2* rd  = (const ulonglong2*)(S.rgdl[b2][g] + 64 * h);
#pragma unroll
            for (int j4 = 0; j4 < 8; j4++) {
                ulonglong2 cgv = cgp[j4];
                ulonglong2 bq0 = rd[2 * j4];
                ulonglong2 bq1 = rd[2 * j4 + 1];
                Mr2[2*j4]   = f2fma(f2mul(Mr2[2*j4],   cgv.x), rgd,
                                    f2mul(kgr[2*j4],   dd));
                Mr2[2*j4+1] = f2fma(f2mul(Mr2[2*j4+1], cgv.y), rgd,
                                    f2mul(kgr[2*j4+1], dd));
                MTr2[2*j4]   = f2fma(f2mul(MTr2[2*j4],   bq0.x), cgd,
                                     f2mul(bq0.y, knd));
                MTr2[2*j4+1] = f2fma(f2mul(MTr2[2*j4+1], bq1.x), cgd,
                                     f2mul(bq1.y, knd));
            }
        }
        if (!g) {
            ull s0 = 0ull, s1 = 0ull;
            const ulonglong2* q2 = (const ulonglong2*)(S.raw[cur] + 384 + 32 * h);
#pragma unroll
            for (int j4 = 0; j4 < 8; j4++) {
                ulonglong2 q = q2[j4];
                s0 = f2fma(Mr2[2 * j4],     q.x, s0);
                s1 = f2fma(Mr2[2 * j4 + 1], q.y, s1);
            }
            float a0, a1, b0, b1;
            upk2(s0, a0, a1); upk2(s1, b0, b1);
            float s = (a0 + a1) + (b0 + b1);
            s += __shfl_xor_sync(0xffffffffu, s, 1);
            if (!h) out[((size_t)t * BATCH + b) * 64 + i] = s * sigm(s);
        }
    }

    if (write_M) {
        float* Mo = out + NOUT + ((size_t)(g * BATCH + b)) * 4096
                    + (size_t)i * 64 + 32 * h;
#pragma unroll
        for (int j = 0; j < 16; j++) {
            float a, c; upk2(Mr2[j], a, c);
            Mo[2 * j] = a; Mo[2 * j + 1] = c;
        }
    }
}

// ---------------------------------------------------------------------------
extern "C" void kernel_launch(void* const* d_in, const int* in_sizes, int n_in,
                              void* d_out, int out_size)
{
    const float *x = nullptr, *Mi = nullptr, *Wkv = nullptr,
                *Wq = nullptr, *Bg = nullptr;
    for (int idx = 0; idx < n_in; idx++) {
        switch (in_sizes[idx]) {
            case 33554432: x   = (const float*)d_in[idx]; break;
            case 196608:   Mi  = (const float*)d_in[idx]; break;
            case 393216:   Wkv = (const float*)d_in[idx]; break;
            case 65536:    Wq  = (const float*)d_in[idx]; break;
            case 192:      Bg  = (const float*)d_in[idx]; break;
        }
    }
    if (!x || !Mi || !Wkv || !Wq || !Bg) {
        x   = (const float*)d_in[0];
        Mi  = (const float*)d_in[1];
        Wkv = (const float*)d_in[2];
        Wq  = (const float*)d_in[3];
        Bg  = (const float*)d_in[4];
    }

    const int write_M = (out_size >= NOUT + MSIZE) ? 1 : 0;

    // Spill-only guard (R14/R15 lesson). Fallback = exact R16 kernel.
    cudaFuncAttributes attr;
    bool useH = true;
    if (cudaFuncGetAttributes(&attr, (const void*)fusedH) == cudaSuccess)
        useH = (attr.localSizeBytes == 0);

    zero_cnt<<<1, 512>>>();
    if (useH)
        fusedH<<<NCTA, 384>>>(x, Wkv, Wq, Mi, Bg, (float*)d_out, write_M);
    else
        fusedG<<<NCTA, 384>>>(x, Wkv, Wq, Mi, Bg, (float*)d_out, write_M);
}